// round 4
// baseline (speedup 1.0000x reference)
#include <cuda_runtime.h>
#include <cstdint>

#define MAXN 20000
#define DEG  32
#define MAXE (MAXN * DEG)
#define GB   148
#define TB   1024

typedef unsigned long long u64;

// ---------------- device state (no dynamic allocation allowed) ----------------
__device__ u64           d_key[MAXN];   // (pathkey << 15) | parent_id ; ~0 = unseen
__device__ float4        d_quat[MAXN];  // node quaternions (w,x,y,z)
__device__ unsigned char d_inv[MAXE];   // per node: rank -> original edge slot
__device__ int           d_totArr[16];  // winners per level
__device__ unsigned      d_barCount;
__device__ unsigned      d_barGen;

// ---------------- per-launch state reset (determinism under graph replay) ----
__global__ void init_kernel(const int* __restrict__ start,
                            float* __restrict__ out, int N, int off) {
    int i = blockIdx.x * blockDim.x + threadIdx.x;
    int s = start[0];
    if (i < N) {
        d_key[i] = (i == s) ? ((1ull << 15) | (u64)s) : ~0ull;  // start pathkey = 1
        float* o = out + off + 4 * i;        // identity default (unreached nodes)
        o[0] = 1.0f; o[1] = 0.0f; o[2] = 0.0f; o[3] = 0.0f;
    }
    if (i == 0) {
        d_quat[s]  = make_float4(1.0f, 0.0f, 0.0f, 0.0f);
        d_barCount = 0;
        d_barGen   = 0;
        #pragma unroll
        for (int l = 0; l < 16; ++l) d_totArr[l] = 0;
    }
    if (i < off) out[i] = (float)s;          // leading scalar output (start_node)
}

// ---------------- software grid barrier (GB co-resident blocks) --------------
__device__ __forceinline__ void grid_barrier() {
    __threadfence();       // publish writes (gpu-scope)
    __syncthreads();
    if (threadIdx.x == 0) {
        volatile unsigned* gen = &d_barGen;
        unsigned g = *gen;
        __threadfence();
        if (atomicAdd(&d_barCount, 1u) == (unsigned)(GB - 1)) {
            d_barCount = 0;
            __threadfence();
            *gen = g + 1;
        } else {
            while (*gen == g) { }
        }
    }
    __syncthreads();
}

// ---------------- fused persistent BFS ---------------------------------------
// key(v) = (pathkey << 15) | parent ; pathkey(child) = pathkey(parent)*32 + rank.
// Level-L pathkeys lie in [2^(5L), 2^(5L+1)) => level = msb(pathkey)/5, ordering
// decided by pathkey alone (payload bits never tie-break: pathkeys unique per
// node), earlier levels always beat later ones under atomicMin. Each level is
// ONE phase: scan nodes for this level's winners; the warp cooperatively
// computes the winner's edge ranks (replacing a standalone sort kernel), writes
// the rank->slot map for its future children, computes the winner's quaternion
// from its decoded parent, and proposes all 32 edges via atomicMin.
__global__ void __launch_bounds__(TB, 1)
bfs_kernel(const float* __restrict__ ea, const int* __restrict__ dst,
           float* __restrict__ out, int off, int N) {
    const int gtid = blockIdx.x * TB + threadIdx.x;
    const int lane = threadIdx.x & 31;

    for (int lvl = 0; lvl < 10; ++lvl) {
        // one node per thread (grid covers N)
        int  v   = gtid;
        u64  k   = (v < N) ? __ldcg(&d_key[v]) : ~0ull;
        bool win = false;
        if (v < N && k != ~0ull) {
            u64 pk  = k >> 15;
            int lev = 63 - __clzll(pk);
            win = (lev == 5 * lvl);
        }
        unsigned m = __ballot_sync(0xffffffffu, win);
        while (m) {
            int srcLane = __ffs(m) - 1; m &= m - 1u;
            int vv = __shfl_sync(0xffffffffu, v, srcLane);
            u64 kk = __shfl_sync(0xffffffffu, k, srcLane);

            // --- cooperative: all 32 lanes handle one edge of winner vv ---
            int   e  = (vv << 5) + lane;
            int   dv = dst[e];
            float wq = reinterpret_cast<const float4*>(ea)[e].x;  // quat w
            unsigned ek = __float_as_uint(
                2.0f * (acosf(fminf(fabsf(wq), 1.0f)) * 57.29577951308232f));
            // stable rank of (err, slot) within the 32 edges
            int rank = 0;
            #pragma unroll
            for (int j = 0; j < 32; ++j) {
                unsigned o = __shfl_sync(0xffffffffu, ek, j);
                rank += (int)((o < ek) | ((o == ek) & (j < lane)));
            }
            d_inv[(vv << 5) + rank] = (unsigned char)lane;  // rank -> slot

            // --- lane 0: winner's quaternion from decoded parent ---
            if (lane == 0 && lvl > 0) {
                int u  = (int)(kk & 0x7FFFu);
                int r  = (int)((kk >> 15) & 31u);
                int jo = (int)__ldcg(&d_inv[(u << 5) + r]);  // parent wrote last phase
                const float4 q = reinterpret_cast<const float4*>(ea)[(u << 5) + jo];
                float4 b = __ldcg(&d_quat[u]);               // final (BFS order)
                float aw = q.x, ax = -q.y, ay = -q.z, az = -q.w;  // conjugate
                float4 rq;
                rq.x = aw * b.x - ax * b.y - ay * b.z - az * b.w; // w
                rq.y = aw * b.y + ax * b.x + ay * b.w - az * b.z; // x
                rq.z = aw * b.z - ax * b.w + ay * b.x + az * b.y; // y
                rq.w = aw * b.w + ax * b.z - ay * b.y + az * b.x; // z
                d_quat[vv] = rq;
                float* o = out + off + 4 * vv;
                o[0] = rq.x; o[1] = rq.y; o[2] = rq.z; o[3] = rq.w;
            }

            // --- propose: child key = (pathkey*32 + rank) << 15 | vv ---
            u64 ck = ((kk >> 15) << 20) | ((u64)rank << 15) | (u64)vv;
            atomicMin(&d_key[dv], ck);
        }

        // winner count for termination (per-level slot: no cross-phase race)
        int bw = __syncthreads_count(win);
        if (threadIdx.x == 0 && bw) atomicAdd(&d_totArr[lvl], bw);
        grid_barrier();
        if (__ldcg(&d_totArr[lvl]) == 0) break;   // uniform across grid
    }
}

// ---------------- launch ------------------------------------------------------
extern "C" void kernel_launch(void* const* d_in, const int* in_sizes, int n_in,
                              void* d_out, int out_size) {
    const float* ea    = (const float*)d_in[0];  // edge_attr [E,4] f32
    const int*   ei    = (const int*)d_in[1];    // edge_index [2,E] i32
    const int*   start = (const int*)d_in[2];    // start_node scalar i32

    int E = in_sizes[0] / 4;
    int N = E / DEG;
    float* out = (float*)d_out;
    int off = out_size - 4 * N;
    if (off < 0) off = 0;

    int t = 256;
    int initN = (N > off) ? N : off;
    init_kernel<<<(initN + t - 1) / t, t>>>(start, out, N, off);
    bfs_kernel<<<GB, TB>>>(ea, ei + E, out, off, N);
}